// round 4
// baseline (speedup 1.0000x reference)
#include <cuda_runtime.h>

#define Tt 2048
#define Bb 512
#define Cc 8
#define Hh 20
#define GRP 8
#define RING 16

typedef unsigned long long u64;

__device__ __forceinline__ u64 pack2(float a, float b) {
    u64 r; asm("mov.b64 %0, {%1, %2};" : "=l"(r) : "f"(a), "f"(b)); return r;
}
__device__ __forceinline__ void unpack2(u64 v, float &a, float &b) {
    asm("mov.b64 {%0, %1}, %2;" : "=f"(a), "=f"(b) : "l"(v));
}
// packed dual-FMA: d.x += a.x*b.x ; d.y += a.y*b.y
__device__ __forceinline__ void ffma2(u64 &d, u64 a, u64 b) {
    asm("fma.rn.f32x2 %0, %1, %2, %0;" : "+l"(d) : "l"(a), "l"(b));
}
__device__ __forceinline__ float hadd2(u64 v) {
    float a, b; unpack2(v, a, b); return a + b;
}
__device__ __forceinline__ float tanhfast(float x) {
    float y; asm("tanh.approx.f32 %0, %1;" : "=f"(y) : "f"(x)); return y;
}
__device__ __forceinline__ float sigmfast(float x) {
    return fmaf(tanhfast(0.5f * x), 0.5f, 0.5f);
}

// 2 warps per batch: role 0 = layer-1 producer (also computes the first 4
// k-pairs of layer-2's input GEMV as a per-lane float4 partial), role 1 =
// layer-2 consumer one GROUP (8 steps) behind through depth-16 smem rings.
// One named barrier per 8 steps; all weights in registers; all smem h reads
// are LDS.128 software-pipelined off the critical path.
__global__ void __launch_bounds__(256, 1) lstm2_kernel(
    const float* __restrict__ x,
    const float* __restrict__ Wih0, const float* __restrict__ Whh0,
    const float* __restrict__ bih0, const float* __restrict__ bhh0,
    const float* __restrict__ Wih1, const float* __restrict__ Whh1,
    const float* __restrict__ bih1, const float* __restrict__ bhh1,
    float* __restrict__ out)
{
    __shared__ __align__(16) float  h1ring[4][RING][24];
    __shared__ __align__(16) float4 partring[4][RING][32];
    __shared__ __align__(16) float  h2buf[4][24];

    const int tid   = threadIdx.x;
    const int w     = tid >> 5;
    const int lane  = tid & 31;
    const int pair  = w >> 1;
    // flip roles on pairs 2,3 so each SMSP hosts one L1 + one L2 warp
    const int role  = (w & 1) ^ ((w >> 2) & 1);
    const int batch = blockIdx.x * 4 + pair;
    const int barid = pair + 1;

    if (role == 0) {
        // -------- layer 1 producer + partial of layer-2 input GEMV --------
        u64 wx[4][4], wh[4][10], wp[4][4], binit[4];
        if (lane < Hh) {
            #pragma unroll
            for (int g = 0; g < 4; g++) {
                const int row = g * Hh + lane;              // gate order i,f,g,o
                const float* rx = Wih0 + row * Cc;
                #pragma unroll
                for (int kp = 0; kp < 4; kp++)  wx[g][kp] = pack2(rx[2*kp], rx[2*kp+1]);
                const float* rh = Whh0 + row * Hh;
                #pragma unroll
                for (int kp = 0; kp < 10; kp++) wh[g][kp] = pack2(rh[2*kp], rh[2*kp+1]);
                const float* rp = Wih1 + row * Hh;          // first 4 k-pairs of W_ih1
                #pragma unroll
                for (int kp = 0; kp < 4; kp++)  wp[g][kp] = pack2(rp[2*kp], rp[2*kp+1]);
                binit[g] = pack2(bih0[row] + bhh0[row], 0.f);
            }
        }
        // x prefetch pipeline, depth 2 (uniform LDG.128 pairs, broadcast)
        const ulonglong2* xb   = ((const ulonglong2*)x) + (size_t)batch * 2;
        ulonglong2 x0a = xb[0],    x0b = xb[1];             // row t
        ulonglong2 x1a = xb[1024], x1b = xb[1025];          // row t+1
        const ulonglong2* xpre = xb + 2 * 1024;             // row t+2
        ulonglong2 hp[5];
        #pragma unroll
        for (int j = 0; j < 5; j++) { hp[j].x = 0ull; hp[j].y = 0ull; }
        float c1 = 0.f;

        #pragma unroll 1
        for (int p = 0; p < Tt / GRP; p++) {
            #pragma unroll
            for (int s = 0; s < GRP; s++) {
                const int t = p * GRP + s;
                u64 xv0 = x0a.x, xv1 = x0a.y, xv2 = x0b.x, xv3 = x0b.y;
                x0a = x1a; x0b = x1b;
                x1a = xpre[0]; x1b = xpre[1];               // prefetch row t+2 (clamped)
                if (t < Tt - 3) xpre += 1024;

                u64 a0 = binit[0], a1 = binit[1], a2 = binit[2], a3 = binit[3];
                ffma2(a0, wx[0][0], xv0); ffma2(a1, wx[1][0], xv0);
                ffma2(a2, wx[2][0], xv0); ffma2(a3, wx[3][0], xv0);
                ffma2(a0, wx[0][1], xv1); ffma2(a1, wx[1][1], xv1);
                ffma2(a2, wx[2][1], xv1); ffma2(a3, wx[3][1], xv1);
                ffma2(a0, wx[0][2], xv2); ffma2(a1, wx[1][2], xv2);
                ffma2(a2, wx[2][2], xv2); ffma2(a3, wx[3][2], xv2);
                ffma2(a0, wx[0][3], xv3); ffma2(a1, wx[1][3], xv3);
                ffma2(a2, wx[2][3], xv3); ffma2(a3, wx[3][3], xv3);
                #pragma unroll
                for (int j = 0; j < 5; j++) {
                    u64 v0 = hp[j].x, v1 = hp[j].y;
                    ffma2(a0, wh[0][2*j],   v0); ffma2(a1, wh[1][2*j],   v0);
                    ffma2(a2, wh[2][2*j],   v0); ffma2(a3, wh[3][2*j],   v0);
                    ffma2(a0, wh[0][2*j+1], v1); ffma2(a1, wh[1][2*j+1], v1);
                    ffma2(a2, wh[2][2*j+1], v1); ffma2(a3, wh[3][2*j+1], v1);
                }
                float ia = sigmfast(hadd2(a0));
                float fa = sigmfast(hadd2(a1));
                float ga = tanhfast(hadd2(a2));
                float oa = sigmfast(hadd2(a3));
                c1 = fmaf(fa, c1, ia * ga);
                float h1 = oa * tanhfast(c1);
                if (lane < Hh) h1ring[pair][t & (RING - 1)][lane] = h1;
                __syncwarp();
                const ulonglong2* rp = (const ulonglong2*)&h1ring[pair][t & (RING - 1)][0];
                hp[0] = rp[0]; hp[1] = rp[1]; hp[2] = rp[2]; hp[3] = rp[3]; hp[4] = rp[4];
                // partial gates2 = sum over first 4 k-pairs of W_ih1 @ h1[t]
                u64 q0 = 0, q1 = 0, q2 = 0, q3 = 0;
                {
                    u64 v0 = hp[0].x, v1 = hp[0].y, v2 = hp[1].x, v3 = hp[1].y;
                    ffma2(q0, wp[0][0], v0); ffma2(q1, wp[1][0], v0);
                    ffma2(q2, wp[2][0], v0); ffma2(q3, wp[3][0], v0);
                    ffma2(q0, wp[0][1], v1); ffma2(q1, wp[1][1], v1);
                    ffma2(q2, wp[2][1], v1); ffma2(q3, wp[3][1], v1);
                    ffma2(q0, wp[0][2], v2); ffma2(q1, wp[1][2], v2);
                    ffma2(q2, wp[2][2], v2); ffma2(q3, wp[3][2], v2);
                    ffma2(q0, wp[0][3], v3); ffma2(q1, wp[1][3], v3);
                    ffma2(q2, wp[2][3], v3); ffma2(q3, wp[3][3], v3);
                }
                float4 part;
                part.x = hadd2(q0); part.y = hadd2(q1);
                part.z = hadd2(q2); part.w = hadd2(q3);
                if (lane < Hh) partring[pair][t & (RING - 1)][lane] = part;
            }
            asm volatile("bar.sync %0, 64;" :: "r"(barid) : "memory");
        }
    } else {
        // -------- layer 2 consumer, one group behind --------
        u64 w1[4][6], w2[4][10];
        float bias[4];
        if (lane < Hh) {
            #pragma unroll
            for (int g = 0; g < 4; g++) {
                const int row = g * Hh + lane;
                const float* r1 = Wih1 + row * Hh;
                #pragma unroll
                for (int kp = 0; kp < 6; kp++)               // k-pairs 4..9
                    w1[g][kp] = pack2(r1[2*(kp+4)], r1[2*(kp+4)+1]);
                const float* r2 = Whh1 + row * Hh;
                #pragma unroll
                for (int kp = 0; kp < 10; kp++)
                    w2[g][kp] = pack2(r2[2*kp], r2[2*kp+1]);
                bias[g] = bih1[row] + bhh1[row];
            }
        }
        ulonglong2 h2v[5];
        #pragma unroll
        for (int j = 0; j < 5; j++) { h2v[j].x = 0ull; h2v[j].y = 0ull; }
        float c2 = 0.f;
        float* outp = out + (size_t)batch * Hh + lane;

        #pragma unroll 1
        for (int p = 0; p < Tt / GRP; p++) {
            asm volatile("bar.sync %0, 64;" :: "r"(barid) : "memory");
            ulonglong2 h1v[5];
            float4 part;
            {
                const int slot = (p * GRP) & (RING - 1);
                const ulonglong2* rp = (const ulonglong2*)&h1ring[pair][slot][0];
                h1v[0] = rp[0]; h1v[1] = rp[1]; h1v[2] = rp[2]; h1v[3] = rp[3]; h1v[4] = rp[4];
                part = partring[pair][slot][lane];
            }
            #pragma unroll
            for (int s = 0; s < GRP; s++) {
                const int t = p * GRP + s;
                u64 a0 = pack2(bias[0] + part.x, 0.f);
                u64 a1 = pack2(bias[1] + part.y, 0.f);
                u64 a2 = pack2(bias[2] + part.z, 0.f);
                u64 a3 = pack2(bias[3] + part.w, 0.f);
                // h1 contribution, k-pairs 4..9 (pairs live in h1v[2..4])
                #pragma unroll
                for (int j = 0; j < 3; j++) {
                    u64 v0 = h1v[2 + j].x, v1 = h1v[2 + j].y;
                    ffma2(a0, w1[0][2*j],   v0); ffma2(a1, w1[1][2*j],   v0);
                    ffma2(a2, w1[2][2*j],   v0); ffma2(a3, w1[3][2*j],   v0);
                    ffma2(a0, w1[0][2*j+1], v1); ffma2(a1, w1[1][2*j+1], v1);
                    ffma2(a2, w1[2][2*j+1], v1); ffma2(a3, w1[3][2*j+1], v1);
                }
                // prefetch next step's h1 pairs + partial (written pre-barrier)
                if (s < GRP - 1) {
                    const int slot = (t + 1) & (RING - 1);
                    const ulonglong2* rp = (const ulonglong2*)&h1ring[pair][slot][0];
                    h1v[0] = rp[0]; h1v[1] = rp[1]; h1v[2] = rp[2];
                    h1v[3] = rp[3]; h1v[4] = rp[4];
                    part = partring[pair][slot][lane];
                }
                // recurrent h2 contribution
                #pragma unroll
                for (int j = 0; j < 5; j++) {
                    u64 v0 = h2v[j].x, v1 = h2v[j].y;
                    ffma2(a0, w2[0][2*j],   v0); ffma2(a1, w2[1][2*j],   v0);
                    ffma2(a2, w2[2][2*j],   v0); ffma2(a3, w2[3][2*j],   v0);
                    ffma2(a0, w2[0][2*j+1], v1); ffma2(a1, w2[1][2*j+1], v1);
                    ffma2(a2, w2[2][2*j+1], v1); ffma2(a3, w2[3][2*j+1], v1);
                }
                float ia = sigmfast(hadd2(a0));
                float fa = sigmfast(hadd2(a1));
                float ga = tanhfast(hadd2(a2));
                float oa = sigmfast(hadd2(a3));
                c2 = fmaf(fa, c2, ia * ga);
                float h2 = oa * tanhfast(c2);
                if (lane < Hh) {
                    *outp = h2;
                    h2buf[pair][lane] = h2;
                }
                outp += Bb * Hh;
                __syncwarp();
                const ulonglong2* rp2 = (const ulonglong2*)&h2buf[pair][0];
                h2v[0] = rp2[0]; h2v[1] = rp2[1]; h2v[2] = rp2[2];
                h2v[3] = rp2[3]; h2v[4] = rp2[4];
            }
        }
    }
}

extern "C" void kernel_launch(void* const* d_in, const int* in_sizes, int n_in,
                              void* d_out, int out_size) {
    lstm2_kernel<<<Bb / 4, 256>>>(
        (const float*)d_in[0],
        (const float*)d_in[1], (const float*)d_in[2],
        (const float*)d_in[3], (const float*)d_in[4],
        (const float*)d_in[5], (const float*)d_in[6],
        (const float*)d_in[7], (const float*)d_in[8],
        (float*)d_out);
}